// round 2
// baseline (speedup 1.0000x reference)
#include <cuda_runtime.h>
#include <math.h>

#define B_   8
#define N1_  4096
#define N2_  4096
#define C_   512
#define P_   256
#define H_   8
#define HD_  64
#define MLP_ 2048
#define M_   (B_*N1_)   // 32768 rows for the token-major GEMMs

// ---------------- device scratch (no runtime allocation allowed) ----------------
// g_k is reused as attention-out / pre-final scratch (dead after kvp_k).
// g_v is reused as xn = l2norm(attn+q)              (dead after kvp_k).
__device__ float g_q [B_*N1_*C_];     // 64 MB   q = x1@Wq + bq + pos_q
__device__ float g_k [B_*N2_*C_];     // 64 MB   k, later xa
__device__ float g_v [B_*N2_*C_];     // 64 MB   v, later xn
__device__ float g_kp[B_*H_*HD_*P_];  // 4 MB    kp[b,h,d,p]
__device__ float g_vp[B_*H_*HD_*P_];  // 4 MB
__device__ float g_h [B_*N1_*MLP_];   // 256 MB  gelu(xn@W1+b1)

// =======================================================================
// Generic 128x128x8 SGEMM, 256 threads, 8x8 microtile, fused epilogues.
// EPI 0: out = acc + bias[n] + extra[(m%4096)*C + n]                (Q proj)
// EPI 1: n<512 -> out(k)=acc+bias+pos_k ; n>=512 -> out2(v)=acc+bias (KV)
// EPI 2: out = gelu_exact(acc + bias[n])                            (MLP-1)
// EPI 3: out = acc + bias[n] + extra[m*N+n]                         (MLP-2+res)
// =======================================================================
template<int EPI>
__global__ __launch_bounds__(256, 2)
void gemm_k(const float* __restrict__ A, const float* __restrict__ Bw,
            const float* __restrict__ bias, const float* __restrict__ extra,
            float* __restrict__ out, float* __restrict__ out2,
            int M, int N, int K)
{
    __shared__ float As[8][128];
    __shared__ float Bs[8][128];
    const int tid = threadIdx.x;
    const int bm = blockIdx.y * 128, bn = blockIdx.x * 128;
    const int tx = tid & 15, ty = tid >> 4;
    const int arow = tid >> 1, akq = (tid & 1) * 4;
    const int brow = tid >> 5, bcol = (tid & 31) * 4;
    const float* Ap = A + (size_t)(bm + arow) * K + akq;
    const float* Bp = Bw + (size_t)brow * N + bn + bcol;

    float acc[8][8];
#pragma unroll
    for (int i = 0; i < 8; i++)
#pragma unroll
        for (int j = 0; j < 8; j++) acc[i][j] = 0.0f;

    for (int k0 = 0; k0 < K; k0 += 8) {
        float4 a  = *(const float4*)Ap; Ap += 8;
        float4 bv = *(const float4*)Bp; Bp += (size_t)8 * N;
        As[akq + 0][arow] = a.x;
        As[akq + 1][arow] = a.y;
        As[akq + 2][arow] = a.z;
        As[akq + 3][arow] = a.w;
        *(float4*)&Bs[brow][bcol] = bv;
        __syncthreads();
#pragma unroll
        for (int kk = 0; kk < 8; kk++) {
            float ar[8], br[8];
            *(float4*)(ar)     = *(const float4*)&As[kk][ty * 8];
            *(float4*)(ar + 4) = *(const float4*)&As[kk][ty * 8 + 4];
            *(float4*)(br)     = *(const float4*)&Bs[kk][tx * 8];
            *(float4*)(br + 4) = *(const float4*)&Bs[kk][tx * 8 + 4];
#pragma unroll
            for (int i = 0; i < 8; i++)
#pragma unroll
                for (int j = 0; j < 8; j++)
                    acc[i][j] = fmaf(ar[i], br[j], acc[i][j]);
        }
        __syncthreads();
    }

#pragma unroll
    for (int i = 0; i < 8; i++) {
        const int m = bm + ty * 8 + i;
#pragma unroll
        for (int j = 0; j < 8; j++) {
            const int n = bn + tx * 8 + j;
            float v = acc[i][j] + bias[n];
            if (EPI == 0) {
                v += extra[(size_t)(m & (N1_ - 1)) * C_ + n];
                out[(size_t)m * N + n] = v;
            } else if (EPI == 1) {
                if (n < C_) {
                    v += extra[(size_t)(m & (N2_ - 1)) * C_ + n];
                    out[(size_t)m * C_ + n] = v;
                } else {
                    out2[(size_t)m * C_ + (n - C_)] = v;
                }
            } else if (EPI == 2) {
                out[(size_t)m * N + n] = 0.5f * v * (1.0f + erff(v * 0.70710678118654752f));
            } else {
                v += extra[(size_t)m * N + n];
                out[(size_t)m * N + n] = v;
            }
        }
    }
}

// =======================================================================
// kp[b,h,d,p] = sum_n k[b,n,h*64+d] * Wp[n,p] + bp[p]   (and same for v)
// grid: (P/64, B*H, 2{k,v}).  Block computes a [64d x 64p] tile over K=4096.
// =======================================================================
__global__ __launch_bounds__(256, 4)
void kvp_k(const float* __restrict__ kin, const float* __restrict__ vin,
           const float* __restrict__ Wp, const float* __restrict__ bp,
           float* __restrict__ kp, float* __restrict__ vp)
{
    __shared__ float At[32][64];
    __shared__ float Bt[32][64];
    const int p0 = blockIdx.x * 64;
    const int bh = blockIdx.y;
    const int b = bh >> 3, h = bh & 7;
    const float* __restrict__ src = blockIdx.z ? vin : kin;
    float* __restrict__ dst = blockIdx.z ? vp : kp;
    const int tid = threadIdx.x;
    const int tx = tid & 15, ty = tid >> 4;

    float acc[4][4];
#pragma unroll
    for (int i = 0; i < 4; i++)
#pragma unroll
        for (int j = 0; j < 4; j++) acc[i][j] = 0.0f;

    for (int n0 = 0; n0 < N2_; n0 += 32) {
#pragma unroll
        for (int i = 0; i < 8; i++) {
            const int idx = tid + i * 256;
            const int nl = idx >> 6, dd = idx & 63;
            At[nl][dd] = src[((size_t)(b * N2_ + n0 + nl)) * C_ + h * 64 + dd];
            Bt[nl][dd] = Wp[(size_t)(n0 + nl) * P_ + p0 + dd];
        }
        __syncthreads();
#pragma unroll
        for (int kk = 0; kk < 32; kk++) {
            float ar[4], br[4];
#pragma unroll
            for (int i = 0; i < 4; i++) ar[i] = At[kk][ty * 4 + i];
#pragma unroll
            for (int j = 0; j < 4; j++) br[j] = Bt[kk][tx * 4 + j];
#pragma unroll
            for (int i = 0; i < 4; i++)
#pragma unroll
                for (int j = 0; j < 4; j++)
                    acc[i][j] = fmaf(ar[i], br[j], acc[i][j]);
        }
        __syncthreads();
    }
#pragma unroll
    for (int i = 0; i < 4; i++)
#pragma unroll
        for (int j = 0; j < 4; j++) {
            const int d = ty * 4 + i, p = p0 + tx * 4 + j;
            dst[((size_t)bh * 64 + d) * P_ + p] = acc[i][j] + bp[p];
        }
}

// =======================================================================
// Fused attention: one CTA handles (b,h) x 64 queries.
// smem: Ks[64][256], VsT[256][68], QsT[64][68], Ss[64][257]  (~213 KB)
// S = Q @ Kp (scaled), softmax over P=256, out = S @ Vp^T.
// Output scatter matches reference's transpose(0,3,1,2).reshape:
//   flat-in-batch index = d*32768 + h*4096 + q.
// =======================================================================
#define ATT_SMEM_FLOATS (64*256 + 256*68 + 64*68 + 64*257)
#define ATT_SMEM_BYTES  (ATT_SMEM_FLOATS * 4)

__global__ __launch_bounds__(256)
void attn_k(const float* __restrict__ temp, float* __restrict__ xa)
{
    extern __shared__ float sm[];
    float* Ks  = sm;                  // [64][256]
    float* VsT = Ks  + 64 * 256;      // [256][68]  (p-major, padded)
    float* QsT = VsT + 256 * 68;      // [64][68]   (d-major, padded)
    float* Ss  = QsT + 64 * 68;       // [64][257]

    const int bh = blockIdx.x;
    const int b = bh >> 3, h = bh & 7;
    const int q0 = blockIdx.y * 64;
    const int tid = threadIdx.x;

    // stage kp (row-major by d)
#pragma unroll 4
    for (int i = 0; i < 64; i++) {
        const int idx = tid + i * 256;
        Ks[idx] = g_kp[(size_t)bh * (HD_ * P_) + idx];
    }
    // stage vp transposed (p-major)
#pragma unroll 4
    for (int i = 0; i < 64; i++) {
        const int idx = tid + i * 256;
        const int d = idx >> 8, p = idx & 255;
        VsT[p * 68 + d] = g_vp[(size_t)bh * (HD_ * P_) + idx];
    }
    // stage Q transposed (d-major): q[b, q0+r, h*64+d]
#pragma unroll 4
    for (int i = 0; i < 16; i++) {
        const int idx = tid + i * 256;
        const int r = idx >> 6, d = idx & 63;
        QsT[d * 68 + r] = g_q[((size_t)(b * N1_ + q0 + r)) * C_ + h * 64 + d];
    }
    __syncthreads();

    const float tscale = temp[h];

    // ---- phase 1: S[64q x 256p] = Q[64x64] @ Kp[64x256], 8x8 per thread ----
    {
        const int tx = tid & 31, ty = tid >> 5;
        float acc[8][8];
#pragma unroll
        for (int i = 0; i < 8; i++)
#pragma unroll
            for (int j = 0; j < 8; j++) acc[i][j] = 0.0f;
#pragma unroll 4
        for (int d = 0; d < 64; d++) {
            float ar[8], br[8];
            *(float4*)(ar)     = *(const float4*)&QsT[d * 68 + ty * 8];
            *(float4*)(ar + 4) = *(const float4*)&QsT[d * 68 + ty * 8 + 4];
            *(float4*)(br)     = *(const float4*)&Ks[d * 256 + tx * 8];
            *(float4*)(br + 4) = *(const float4*)&Ks[d * 256 + tx * 8 + 4];
#pragma unroll
            for (int i = 0; i < 8; i++)
#pragma unroll
                for (int j = 0; j < 8; j++)
                    acc[i][j] = fmaf(ar[i], br[j], acc[i][j]);
        }
#pragma unroll
        for (int i = 0; i < 8; i++)
#pragma unroll
            for (int j = 0; j < 8; j++)
                Ss[(ty * 8 + i) * 257 + tx * 8 + j] = acc[i][j] * tscale;
    }
    __syncthreads();

    // ---- softmax over P=256 per row; 4 lanes per row ----
    {
        const int r = tid >> 2, seg = tid & 3;
        float* row = Ss + r * 257 + seg * 64;
        float mx = -1e30f;
#pragma unroll 8
        for (int j = 0; j < 64; j++) mx = fmaxf(mx, row[j]);
        mx = fmaxf(mx, __shfl_xor_sync(0xffffffffu, mx, 1));
        mx = fmaxf(mx, __shfl_xor_sync(0xffffffffu, mx, 2));
        float s = 0.0f;
#pragma unroll 8
        for (int j = 0; j < 64; j++) {
            const float e = __expf(row[j] - mx);
            row[j] = e;
            s += e;
        }
        s += __shfl_xor_sync(0xffffffffu, s, 1);
        s += __shfl_xor_sync(0xffffffffu, s, 2);
        const float inv = 1.0f / s;
#pragma unroll 8
        for (int j = 0; j < 64; j++) row[j] *= inv;
    }
    __syncthreads();

    // ---- phase 2: out[64q x 64d] = S[64x256] @ Vp^T, 4x4 per thread ----
    {
        const int tx = tid & 15, ty = tid >> 4;  // tx->q group, ty->d group
        float acc[4][4];                         // [i=q][j=d]
#pragma unroll
        for (int i = 0; i < 4; i++)
#pragma unroll
            for (int j = 0; j < 4; j++) acc[i][j] = 0.0f;
#pragma unroll 4
        for (int p = 0; p < 256; p++) {
            float ar[4], br[4];
#pragma unroll
            for (int i = 0; i < 4; i++) ar[i] = Ss[(tx * 4 + i) * 257 + p];
            *(float4*)br = *(const float4*)&VsT[p * 68 + ty * 4];
#pragma unroll
            for (int i = 0; i < 4; i++)
#pragma unroll
                for (int j = 0; j < 4; j++)
                    acc[i][j] = fmaf(ar[i], br[j], acc[i][j]);
        }
        // scatter: xa[b][d*32768 + h*4096 + q], coalesced float4 along q
        const size_t base = (size_t)b * (N1_ * C_) + (size_t)h * N1_ + q0 + tx * 4;
#pragma unroll
        for (int j = 0; j < 4; j++) {
            float4 o = make_float4(acc[0][j], acc[1][j], acc[2][j], acc[3][j]);
            *(float4*)&xa[base + (size_t)(ty * 4 + j) * (H_ * N1_)] = o;
        }
    }
}

// =======================================================================
// Row-wise L2 norm over C=512: out = (a [+ b]) / max(||.||, 1e-12)
// one warp per row, 8 rows per block.
// =======================================================================
__global__ __launch_bounds__(256)
void l2n_k(const float* __restrict__ a, const float* __restrict__ bb,
           float* __restrict__ out)
{
    const int row = blockIdx.x * 8 + (threadIdx.x >> 5);
    const int lane = threadIdx.x & 31;
    const float4* pa = (const float4*)(a + (size_t)row * C_);
    const float4* pb = bb ? (const float4*)(bb + (size_t)row * C_) : nullptr;
    float4 v[4];
    float ss = 0.0f;
#pragma unroll
    for (int i = 0; i < 4; i++) {
        float4 t = pa[lane + 32 * i];
        if (pb) {
            float4 u = pb[lane + 32 * i];
            t.x += u.x; t.y += u.y; t.z += u.z; t.w += u.w;
        }
        v[i] = t;
        ss += t.x * t.x + t.y * t.y + t.z * t.z + t.w * t.w;
    }
#pragma unroll
    for (int o = 16; o > 0; o >>= 1) ss += __shfl_xor_sync(0xffffffffu, ss, o);
    const float inv = 1.0f / fmaxf(sqrtf(ss), 1e-12f);
    float4* po = (float4*)(out + (size_t)row * C_);
#pragma unroll
    for (int i = 0; i < 4; i++) {
        v[i].x *= inv; v[i].y *= inv; v[i].z *= inv; v[i].w *= inv;
        po[lane + 32 * i] = v[i];
    }
}

// =======================================================================
extern "C" void kernel_launch(void* const* d_in, const int* in_sizes, int n_in,
                              void* d_out, int out_size)
{
    const float* x1    = (const float*)d_in[0];
    const float* x2    = (const float*)d_in[1];
    const float* Wq    = (const float*)d_in[2];
    const float* bq    = (const float*)d_in[3];
    const float* Wkv   = (const float*)d_in[4];
    const float* bkv   = (const float*)d_in[5];
    const float* Wp    = (const float*)d_in[6];
    const float* bp    = (const float*)d_in[7];
    const float* pos_q = (const float*)d_in[8];
    const float* pos_k = (const float*)d_in[9];
    const float* temp  = (const float*)d_in[10];
    const float* W1    = (const float*)d_in[11];
    const float* b1    = (const float*)d_in[12];
    const float* W2    = (const float*)d_in[13];
    const float* b2    = (const float*)d_in[14];

    float *q, *k, *v, *kp, *vp, *hh;
    cudaGetSymbolAddress((void**)&q,  g_q);
    cudaGetSymbolAddress((void**)&k,  g_k);
    cudaGetSymbolAddress((void**)&v,  g_v);
    cudaGetSymbolAddress((void**)&kp, g_kp);
    cudaGetSymbolAddress((void**)&vp, g_vp);
    cudaGetSymbolAddress((void**)&hh, g_h);
    float* xa = k;   // reuse: k dead after kvp_k
    float* xn = v;   // reuse: v dead after kvp_k

    cudaFuncSetAttribute(attn_k, cudaFuncAttributeMaxDynamicSharedMemorySize,
                         ATT_SMEM_BYTES);

    // 1) q = x1 @ Wq + bq + pos_q
    gemm_k<0><<<dim3(C_ / 128, M_ / 128), 256>>>(x1, Wq, bq, pos_q, q, nullptr,
                                                 M_, C_, C_);
    // 2) kv = x2 @ Wkv + bkv ; k += pos_k ; split k/v
    gemm_k<1><<<dim3(2 * C_ / 128, M_ / 128), 256>>>(x2, Wkv, bkv, pos_k, k, v,
                                                     M_, 2 * C_, C_);
    // 3) kp/vp = einsum('bhnd,np->bhdp') + bp
    kvp_k<<<dim3(P_ / 64, B_ * H_, 2), 256>>>(k, v, Wp, bp, kp, vp);
    // 4) fused attention (QK, softmax, AV, scatter). Writes xa (= g_k, now dead).
    attn_k<<<dim3(B_ * H_, N1_ / 64), 256, ATT_SMEM_BYTES>>>(temp, xa);
    // 5) xn = l2norm(attn_out + q)   (xn = g_v, now dead)
    l2n_k<<<M_ / 8, 256>>>(xa, q, xn);
    // 6) h = gelu(xn @ W1 + b1)
    gemm_k<2><<<dim3(MLP_ / 128, M_ / 128), 256>>>(xn, W1, b1, nullptr, hh,
                                                   nullptr, M_, MLP_, C_);
    // 7) pre = h @ W2 + b2 + xn   (reuse xa as scratch)
    gemm_k<3><<<dim3(C_ / 128, M_ / 128), 256>>>(hh, W2, b2, xn, xa, nullptr,
                                                 M_, C_, MLP_);
    // 8) out = l2norm(pre)
    l2n_k<<<M_ / 8, 256>>>(xa, nullptr, (float*)d_out);
}

// round 4
// speedup vs baseline: 2.0050x; 2.0050x over previous
#include <cuda_runtime.h>
#include <math.h>
#include <stdint.h>

#define B_   8
#define N1_  4096
#define N2_  4096
#define C_   512
#define P_   256
#define H_   8
#define HD_  64
#define MLP_ 2048
#define M_   (B_*N1_)

typedef unsigned short u16;

// ---------------- device scratch ----------------
__device__ float g_q [B_*N1_*C_];
__device__ float g_k [B_*N2_*C_];     // k, later xa
__device__ float g_v [B_*N2_*C_];     // v, later xn
__device__ float g_kp[B_*H_*HD_*P_];
__device__ float g_vp[B_*H_*HD_*P_];
// bf16-split activations
__device__ u16 g_x1h[M_*C_], g_x1l[M_*C_];
__device__ u16 g_x2h[M_*C_], g_x2l[M_*C_];
__device__ u16 g_xnh[M_*C_], g_xnl[M_*C_];
__device__ u16 g_hh [M_*MLP_], g_hl [M_*MLP_];
// transposed + bf16-split weights: Wt[n][k]
__device__ u16 g_wq_hi [C_*C_],   g_wq_lo [C_*C_];
__device__ u16 g_wkv_hi[2*C_*C_], g_wkv_lo[2*C_*C_];
__device__ u16 g_w1_hi [MLP_*C_], g_w1_lo [MLP_*C_];
__device__ u16 g_w2_hi [C_*MLP_], g_w2_lo [C_*MLP_];

// ======================= helpers =======================
__device__ __forceinline__ uint32_t smem_u32(const void* p) {
    uint32_t a;
    asm("{ .reg .u64 t; cvta.to.shared.u64 t, %1; cvt.u32.u64 %0, t; }"
        : "=r"(a) : "l"(p));
    return a;
}
#define SWZ(b) ((b) ^ (((b) >> 3) & 0x70))
#define CPA16(dst, src) asm volatile( \
    "cp.async.cg.shared.global [%0], [%1], 16;" :: "r"(dst), "l"(src))
#define CPA_COMMIT() asm volatile("cp.async.commit_group;" ::: "memory")
#define CPA_WAIT1()  asm volatile("cp.async.wait_group 1;" ::: "memory")

__device__ __forceinline__ void ldsm_x4(uint32_t& r0, uint32_t& r1,
                                        uint32_t& r2, uint32_t& r3, uint32_t a) {
    asm volatile("ldmatrix.sync.aligned.m8n8.x4.shared.b16 {%0,%1,%2,%3}, [%4];"
                 : "=r"(r0), "=r"(r1), "=r"(r2), "=r"(r3) : "r"(a));
}
__device__ __forceinline__ void mma_bf16(float* c, uint32_t a0, uint32_t a1,
                                         uint32_t a2, uint32_t a3,
                                         uint32_t b0, uint32_t b1) {
    asm volatile(
        "mma.sync.aligned.m16n8k16.row.col.f32.bf16.bf16.f32 "
        "{%0,%1,%2,%3}, {%4,%5,%6,%7}, {%8,%9}, {%0,%1,%2,%3};"
        : "+f"(c[0]), "+f"(c[1]), "+f"(c[2]), "+f"(c[3])
        : "r"(a0), "r"(a1), "r"(a2), "r"(a3), "r"(b0), "r"(b1));
}
__device__ __forceinline__ void bsplit(float a, uint32_t& hi, uint32_t& lo) {
    uint32_t u = __float_as_uint(a);
    uint32_t hr = (u + 0x7fffu + ((u >> 16) & 1u)) & 0xffff0000u;
    hi = hr >> 16;
    float l = a - __uint_as_float(hr);
    uint32_t ul = __float_as_uint(l);
    lo = (ul + 0x7fffu + ((ul >> 16) & 1u)) >> 16;
}

// =======================================================================
// Weight transpose + bf16 split: W[K][N] fp32 -> Wt_hi/lo[N][K] bf16
// =======================================================================
__global__ __launch_bounds__(256)
void wsplit_k(const float* __restrict__ W, u16* __restrict__ hi,
              u16* __restrict__ lo, int K, int N)
{
    __shared__ float tile[32][33];
    const int n0 = blockIdx.x * 32, k0 = blockIdx.y * 32;
    const int tx = threadIdx.x & 31, ty = threadIdx.x >> 5;
#pragma unroll
    for (int r = 0; r < 4; r++)
        tile[ty + 8 * r][tx] = W[(size_t)(k0 + ty + 8 * r) * N + n0 + tx];
    __syncthreads();
#pragma unroll
    for (int r = 0; r < 4; r++) {
        const int n = n0 + ty + 8 * r, k = k0 + tx;
        uint32_t h, l;
        bsplit(tile[tx][ty + 8 * r], h, l);
        hi[(size_t)n * K + k] = (u16)h;
        lo[(size_t)n * K + k] = (u16)l;
    }
}

// =======================================================================
// Activation bf16 split: A fp32 [n] -> hi/lo bf16 [n] (same layout)
// =======================================================================
__global__ __launch_bounds__(256)
void asplit_k(const float* __restrict__ A, u16* __restrict__ hi,
              u16* __restrict__ lo)
{
    const size_t i4 = ((size_t)blockIdx.x * 256 + threadIdx.x) * 4;
    float4 f = *(const float4*)(A + i4);
    uint32_t h0, l0, h1, l1, h2, l2, h3, l3;
    bsplit(f.x, h0, l0); bsplit(f.y, h1, l1);
    bsplit(f.z, h2, l2); bsplit(f.w, h3, l3);
    *(uint2*)(hi + i4) = make_uint2(h0 | (h1 << 16), h2 | (h3 << 16));
    *(uint2*)(lo + i4) = make_uint2(l0 | (l1 << 16), l2 | (l3 << 16));
}

// =======================================================================
// bf16x3 HMMA GEMM via mma.sync: D[128m x 128n] per CTA.
// A pre-split bf16 [M][K]; B pre-split bf16 [N][K].
// 3-stage cp.async pipeline. 256 threads, 8 warps (2m x 4n), warp tile 64x32.
// EPI 0: out=acc+bias+pos_q         (fp32)
// EPI 1: split k (+pos_k) / v      (fp32)
// EPI 2: gelu -> bf16 hi/lo split  (u16 out/out2)
// EPI 3: out=acc+bias+extra        (fp32)
// =======================================================================
#define TG_SMEM (3 * 65536)

template<int EPI>
__global__ __launch_bounds__(256, 1)
void tgemm(const u16* __restrict__ Ahi, const u16* __restrict__ Alo,
           const u16* __restrict__ Bhi, const u16* __restrict__ Blo,
           const float* __restrict__ bias, const float* __restrict__ extra,
           void* __restrict__ out, void* __restrict__ out2,
           int M, int N, int K)
{
    extern __shared__ __align__(1024) char sm_raw[];
    const uint32_t sb = smem_u32(sm_raw);
    const int tid = threadIdx.x;
    const int wid = tid >> 5, lane = tid & 31;
    const int bm = blockIdx.y * 128, bn = blockIdx.x * 128;
    const int wm = (wid & 1) * 64, wn = (wid >> 1) * 32;
    const int nck = K >> 6;

    float acc[4][4][4];
#pragma unroll
    for (int i = 0; i < 4; i++)
#pragma unroll
        for (int j = 0; j < 4; j++)
#pragma unroll
            for (int r = 0; r < 4; r++) acc[i][j][r] = 0.0f;

    // ldmatrix lane-address components
    const int a_row = ((lane >> 3) & 1) * 8 + (lane & 7);
    const int a_col = (lane >> 4) * 8;
    const int b_row = (lane >> 4) * 8 + (lane & 7);
    const int b_col = ((lane >> 3) & 1) * 8;

    auto load_stage = [&](int ck, int stage) {
        if (ck < nck) {
            const int k0 = ck * 64;
            const uint32_t sbase = sb + stage * 65536;
#pragma unroll
            for (int i = 0; i < 4; i++) {
                const int id = tid + i * 256;
                const int row = id >> 3, c16 = id & 7;
                const uint32_t dsw = SWZ((uint32_t)(row * 128 + c16 * 16));
                const size_t asrc = (size_t)(bm + row) * K + k0 + c16 * 8;
                const size_t bsrc = (size_t)(bn + row) * K + k0 + c16 * 8;
                CPA16(sbase + dsw,         Ahi + asrc);
                CPA16(sbase + 16384 + dsw, Alo + asrc);
                CPA16(sbase + 32768 + dsw, Bhi + bsrc);
                CPA16(sbase + 49152 + dsw, Blo + bsrc);
            }
        }
        CPA_COMMIT();
    };

    load_stage(0, 0);
    load_stage(1, 1);

    for (int ck = 0; ck < nck; ck++) {
        CPA_WAIT1();
        __syncthreads();
        load_stage(ck + 2, (ck + 2) % 3);

        const uint32_t base = sb + (ck % 3) * 65536;
#pragma unroll
        for (int ks = 0; ks < 4; ks++) {
            const int kk = ks * 16;
            uint32_t ah[4][4], al[4][4], bh[2][4], bl[2][4];
#pragma unroll
            for (int mf = 0; mf < 4; mf++) {
                const uint32_t ao = SWZ((uint32_t)((wm + mf * 16 + a_row) * 128 +
                                                   (kk + a_col) * 2));
                ldsm_x4(ah[mf][0], ah[mf][1], ah[mf][2], ah[mf][3], base + ao);
                ldsm_x4(al[mf][0], al[mf][1], al[mf][2], al[mf][3],
                        base + 16384 + ao);
            }
#pragma unroll
            for (int p = 0; p < 2; p++) {
                const uint32_t bo = SWZ((uint32_t)((wn + p * 16 + b_row) * 128 +
                                                   (kk + b_col) * 2));
                ldsm_x4(bh[p][0], bh[p][1], bh[p][2], bh[p][3], base + 32768 + bo);
                ldsm_x4(bl[p][0], bl[p][1], bl[p][2], bl[p][3], base + 49152 + bo);
            }
#pragma unroll
            for (int mf = 0; mf < 4; mf++)
#pragma unroll
                for (int p = 0; p < 2; p++)
#pragma unroll
                    for (int s = 0; s < 2; s++) {
                        float* c = acc[mf][p * 2 + s];
                        mma_bf16(c, ah[mf][0], ah[mf][1], ah[mf][2], ah[mf][3],
                                 bh[p][s * 2], bh[p][s * 2 + 1]);
                        mma_bf16(c, al[mf][0], al[mf][1], al[mf][2], al[mf][3],
                                 bh[p][s * 2], bh[p][s * 2 + 1]);
                        mma_bf16(c, ah[mf][0], ah[mf][1], ah[mf][2], ah[mf][3],
                                 bl[p][s * 2], bl[p][s * 2 + 1]);
                    }
        }
    }

    // ---- epilogue ----
    const int l4 = lane >> 2, l2 = (lane & 3) * 2;
#pragma unroll
    for (int mf = 0; mf < 4; mf++)
#pragma unroll
        for (int nf = 0; nf < 4; nf++) {
            const int col = bn + wn + nf * 8 + l2;
            const float bia0 = bias[col], bia1 = bias[col + 1];
#pragma unroll
            for (int half = 0; half < 2; half++) {
                const int m = bm + wm + mf * 16 + l4 + half * 8;
                float v0 = acc[mf][nf][half * 2]     + bia0;
                float v1 = acc[mf][nf][half * 2 + 1] + bia1;
                if (EPI == 0) {
                    v0 += extra[(size_t)(m & (N1_ - 1)) * C_ + col];
                    v1 += extra[(size_t)(m & (N1_ - 1)) * C_ + col + 1];
                    *(float2*)((float*)out + (size_t)m * N + col) = make_float2(v0, v1);
                } else if (EPI == 1) {
                    if (col < C_) {
                        v0 += extra[(size_t)(m & (N2_ - 1)) * C_ + col];
                        v1 += extra[(size_t)(m & (N2_ - 1)) * C_ + col + 1];
                        *(float2*)((float*)out + (size_t)m * C_ + col) = make_float2(v0, v1);
                    } else {
                        *(float2*)((float*)out2 + (size_t)m * C_ + col - C_) = make_float2(v0, v1);
                    }
                } else if (EPI == 2) {
                    v0 = 0.5f * v0 * (1.0f + erff(v0 * 0.70710678118654752f));
                    v1 = 0.5f * v1 * (1.0f + erff(v1 * 0.70710678118654752f));
                    uint32_t h0, l0, h1, l1;
                    bsplit(v0, h0, l0); bsplit(v1, h1, l1);
                    *(uint32_t*)((u16*)out  + (size_t)m * N + col) = h0 | (h1 << 16);
                    *(uint32_t*)((u16*)out2 + (size_t)m * N + col) = l0 | (l1 << 16);
                } else {
                    v0 += extra[(size_t)m * N + col];
                    v1 += extra[(size_t)m * N + col + 1];
                    *(float2*)((float*)out + (size_t)m * N + col) = make_float2(v0, v1);
                }
            }
        }
}

// =======================================================================
// kp[b,h,d,p] = sum_n k[b,n,h*64+d] * Wp[n,p] + bp[p]  (fp32)
// =======================================================================
__global__ __launch_bounds__(256, 4)
void kvp_k(const float* __restrict__ kin, const float* __restrict__ vin,
           const float* __restrict__ Wp, const float* __restrict__ bp,
           float* __restrict__ kp, float* __restrict__ vp)
{
    __shared__ float At[32][64];
    __shared__ float Bt[32][64];
    const int p0 = blockIdx.x * 64;
    const int bh = blockIdx.y;
    const int b = bh >> 3, h = bh & 7;
    const float* __restrict__ src = blockIdx.z ? vin : kin;
    float* __restrict__ dst = blockIdx.z ? vp : kp;
    const int tid = threadIdx.x;
    const int tx = tid & 15, ty = tid >> 4;

    float acc[4][4];
#pragma unroll
    for (int i = 0; i < 4; i++)
#pragma unroll
        for (int j = 0; j < 4; j++) acc[i][j] = 0.0f;

    for (int n0 = 0; n0 < N2_; n0 += 32) {
#pragma unroll
        for (int i = 0; i < 8; i++) {
            const int idx = tid + i * 256;
            const int nl = idx >> 6, dd = idx & 63;
            At[nl][dd] = src[((size_t)(b * N2_ + n0 + nl)) * C_ + h * 64 + dd];
            Bt[nl][dd] = Wp[(size_t)(n0 + nl) * P_ + p0 + dd];
        }
        __syncthreads();
#pragma unroll
        for (int kk = 0; kk < 32; kk++) {
            float ar[4], br[4];
#pragma unroll
            for (int i = 0; i < 4; i++) ar[i] = At[kk][ty * 4 + i];
#pragma unroll
            for (int j = 0; j < 4; j++) br[j] = Bt[kk][tx * 4 + j];
#pragma unroll
            for (int i = 0; i < 4; i++)
#pragma unroll
                for (int j = 0; j < 4; j++)
                    acc[i][j] = fmaf(ar[i], br[j], acc[i][j]);
        }
        __syncthreads();
    }
#pragma unroll
    for (int i = 0; i < 4; i++)
#pragma unroll
        for (int j = 0; j < 4; j++) {
            const int d = ty * 4 + i, p = p0 + tx * 4 + j;
            dst[((size_t)bh * 64 + d) * P_ + p] = acc[i][j] + bp[p];
        }
}

// =======================================================================
// Fused attention (fp32)
// =======================================================================
#define ATT_SMEM_FLOATS (64*256 + 256*68 + 64*68 + 64*257)
#define ATT_SMEM_BYTES  (ATT_SMEM_FLOATS * 4)

__global__ __launch_bounds__(256)
void attn_k(const float* __restrict__ temp, float* __restrict__ xa)
{
    extern __shared__ float sm[];
    float* Ks  = sm;
    float* VsT = Ks  + 64 * 256;
    float* QsT = VsT + 256 * 68;
    float* Ss  = QsT + 64 * 68;

    const int bh = blockIdx.x;
    const int b = bh >> 3, h = bh & 7;
    const int q0 = blockIdx.y * 64;
    const int tid = threadIdx.x;

#pragma unroll 4
    for (int i = 0; i < 64; i++) {
        const int idx = tid + i * 256;
        Ks[idx] = g_kp[(size_t)bh * (HD_ * P_) + idx];
    }
#pragma unroll 4
    for (int i = 0; i < 64; i++) {
        const int idx = tid + i * 256;
        const int d = idx >> 8, p = idx & 255;
        VsT[p * 68 + d] = g_vp[(size_t)bh * (HD_ * P_) + idx];
    }
#pragma unroll 4
    for (int i = 0; i < 16; i++) {
        const int idx = tid + i * 256;
        const int r = idx >> 6, d = idx & 63;
        QsT[d * 68 + r] = g_q[((size_t)(b * N1_ + q0 + r)) * C_ + h * 64 + d];
    }
    __syncthreads();

    const float tscale = temp[h];

    {
        const int tx = tid & 31, ty = tid >> 5;
        float acc[8][8];
#pragma unroll
        for (int i = 0; i < 8; i++)
#pragma unroll
            for (int j = 0; j < 8; j++) acc[i][j] = 0.0f;
#pragma unroll 4
        for (int d = 0; d < 64; d++) {
            float ar[8], br[8];
            *(float4*)(ar)     = *(const float4*)&QsT[d * 68 + ty * 8];
            *(float4*)(ar + 4) = *(const float4*)&QsT[d * 68 + ty * 8 + 4];
            *(float4*)(br)     = *(const float4*)&Ks[d * 256 + tx * 8];
            *(float4*)(br + 4) = *(const float4*)&Ks[d * 256 + tx * 8 + 4];
#pragma unroll
            for (int i = 0; i < 8; i++)
#pragma unroll
                for (int j = 0; j < 8; j++)
                    acc[i][j] = fmaf(ar[i], br[j], acc[i][j]);
        }
#pragma unroll
        for (int i = 0; i < 8; i++)
#pragma unroll
            for (int j = 0; j < 8; j++)
                Ss[(ty * 8 + i) * 257 + tx * 8 + j] = acc[i][j] * tscale;
    }
    __syncthreads();

    {
        const int r = tid >> 2, seg = tid & 3;
        float* row = Ss + r * 257 + seg * 64;
        float mx = -1e30f;
#pragma unroll 8
        for (int j = 0; j < 64; j++) mx = fmaxf(mx, row[j]);
        mx = fmaxf(mx, __shfl_xor_sync(0xffffffffu, mx, 1));
        mx = fmaxf(mx, __shfl_xor_sync(0xffffffffu, mx, 2));
        float s = 0.0f;
#pragma unroll 8
        for (int j = 0; j < 64; j++) {
            const float e = __expf(row[j] - mx);
            row[j] = e;
            s += e;
        }
        s += __shfl_xor_sync(0xffffffffu, s, 1);
        s += __shfl_xor_sync(0xffffffffu, s, 2);
        const float inv = 1.0f / s;
#pragma unroll 8
        for (int j = 0; j < 64; j++) row[j] *= inv;
    }
    __syncthreads();

    {
        const int tx = tid & 15, ty = tid >> 4;
        float acc[4][4];
#pragma unroll
        for (int i = 0; i < 4; i++)
#pragma unroll
            for (int j = 0; j < 4; j++) acc[i][j] = 0.0f;
#pragma unroll 4
        for (int p = 0; p < 256; p++) {
            float ar[4], br[4];
#pragma unroll
            for (int i = 0; i < 4; i++) ar[i] = Ss[(tx * 4 + i) * 257 + p];
            *(float4*)br = *(const float4*)&VsT[p * 68 + ty * 4];
#pragma unroll
            for (int i = 0; i < 4; i++)
#pragma unroll
                for (int j = 0; j < 4; j++)
                    acc[i][j] = fmaf(ar[i], br[j], acc[i][j]);
        }
        const size_t base = (size_t)b * (N1_ * C_) + (size_t)h * N1_ + q0 + tx * 4;
#pragma unroll
        for (int j = 0; j < 4; j++) {
            float4 o = make_float4(acc[0][j], acc[1][j], acc[2][j], acc[3][j]);
            *(float4*)&xa[base + (size_t)(ty * 4 + j) * (H_ * N1_)] = o;
        }
    }
}

// =======================================================================
// Row-wise L2 norm over C=512; optional bf16 split side-output.
// =======================================================================
__global__ __launch_bounds__(256)
void l2n_k(const float* __restrict__ a, const float* __restrict__ bb,
           float* __restrict__ out, u16* __restrict__ oh, u16* __restrict__ ol)
{
    const int row = blockIdx.x * 8 + (threadIdx.x >> 5);
    const int lane = threadIdx.x & 31;
    const float4* pa = (const float4*)(a + (size_t)row * C_);
    const float4* pb = bb ? (const float4*)(bb + (size_t)row * C_) : nullptr;
    float4 v[4];
    float ss = 0.0f;
#pragma unroll
    for (int i = 0; i < 4; i++) {
        float4 t = pa[lane + 32 * i];
        if (pb) {
            float4 u = pb[lane + 32 * i];
            t.x += u.x; t.y += u.y; t.z += u.z; t.w += u.w;
        }
        v[i] = t;
        ss += t.x * t.x + t.y * t.y + t.z * t.z + t.w * t.w;
    }
#pragma unroll
    for (int o = 16; o > 0; o >>= 1) ss += __shfl_xor_sync(0xffffffffu, ss, o);
    const float inv = 1.0f / fmaxf(sqrtf(ss), 1e-12f);
    float4* po = (float4*)(out + (size_t)row * C_);
#pragma unroll
    for (int i = 0; i < 4; i++) {
        v[i].x *= inv; v[i].y *= inv; v[i].z *= inv; v[i].w *= inv;
        po[lane + 32 * i] = v[i];
        if (oh) {
            uint32_t h0, l0, h1, l1, h2, l2, h3, l3;
            bsplit(v[i].x, h0, l0); bsplit(v[i].y, h1, l1);
            bsplit(v[i].z, h2, l2); bsplit(v[i].w, h3, l3);
            const size_t off = (size_t)row * C_ + (lane + 32 * i) * 4;
            *(uint2*)(oh + off) = make_uint2(h0 | (h1 << 16), h2 | (h3 << 16));
            *(uint2*)(ol + off) = make_uint2(l0 | (l1 << 16), l2 | (l3 << 16));
        }
    }
}

// =======================================================================
extern "C" void kernel_launch(void* const* d_in, const int* in_sizes, int n_in,
                              void* d_out, int out_size)
{
    const float* x1    = (const float*)d_in[0];
    const float* x2    = (const float*)d_in[1];
    const float* Wq    = (const float*)d_in[2];
    const float* bq    = (const float*)d_in[3];
    const float* Wkv   = (const float*)d_in[4];
    const float* bkv   = (const float*)d_in[5];
    const float* Wp    = (const float*)d_in[6];
    const float* bp    = (const float*)d_in[7];
    const float* pos_q = (const float*)d_in[8];
    const float* pos_k = (const float*)d_in[9];
    const float* temp  = (const float*)d_in[10];
    const float* W1    = (const float*)d_in[11];
    const float* b1    = (const float*)d_in[12];
    const float* W2    = (const float*)d_in[13];
    const float* b2    = (const float*)d_in[14];

    float *q, *k, *v, *kp, *vp;
    u16 *x1h, *x1l, *x2h, *x2l, *xnh, *xnl, *hh, *hl;
    u16 *wqh, *wql, *wkvh, *wkvl, *w1h, *w1l, *w2h, *w2l;
    cudaGetSymbolAddress((void**)&q,  g_q);
    cudaGetSymbolAddress((void**)&k,  g_k);
    cudaGetSymbolAddress((void**)&v,  g_v);
    cudaGetSymbolAddress((void**)&kp, g_kp);
    cudaGetSymbolAddress((void**)&vp, g_vp);
    cudaGetSymbolAddress((void**)&x1h, g_x1h); cudaGetSymbolAddress((void**)&x1l, g_x1l);
    cudaGetSymbolAddress((void**)&x2h, g_x2h); cudaGetSymbolAddress((void**)&x2l, g_x2l);
    cudaGetSymbolAddress((void**)&xnh, g_xnh); cudaGetSymbolAddress((void**)&xnl, g_xnl);
    cudaGetSymbolAddress((void**)&hh,  g_hh);  cudaGetSymbolAddress((void**)&hl,  g_hl);
    cudaGetSymbolAddress((void**)&wqh,  g_wq_hi);  cudaGetSymbolAddress((void**)&wql,  g_wq_lo);
    cudaGetSymbolAddress((void**)&wkvh, g_wkv_hi); cudaGetSymbolAddress((void**)&wkvl, g_wkv_lo);
    cudaGetSymbolAddress((void**)&w1h,  g_w1_hi);  cudaGetSymbolAddress((void**)&w1l,  g_w1_lo);
    cudaGetSymbolAddress((void**)&w2h,  g_w2_hi);  cudaGetSymbolAddress((void**)&w2l,  g_w2_lo);
    float* xa = k;   // reuse: k dead after kvp_k
    float* xn = v;   // reuse: v dead after kvp_k

    cudaFuncSetAttribute(attn_k, cudaFuncAttributeMaxDynamicSharedMemorySize, ATT_SMEM_BYTES);
    cudaFuncSetAttribute(tgemm<0>, cudaFuncAttributeMaxDynamicSharedMemorySize, TG_SMEM);
    cudaFuncSetAttribute(tgemm<1>, cudaFuncAttributeMaxDynamicSharedMemorySize, TG_SMEM);
    cudaFuncSetAttribute(tgemm<2>, cudaFuncAttributeMaxDynamicSharedMemorySize, TG_SMEM);
    cudaFuncSetAttribute(tgemm<3>, cudaFuncAttributeMaxDynamicSharedMemorySize, TG_SMEM);

    // 0) splits: weights (transpose) + input activations
    wsplit_k<<<dim3(C_ / 32, C_ / 32), 256>>>(Wq, wqh, wql, C_, C_);
    wsplit_k<<<dim3(2 * C_ / 32, C_ / 32), 256>>>(Wkv, wkvh, wkvl, C_, 2 * C_);
    wsplit_k<<<dim3(MLP_ / 32, C_ / 32), 256>>>(W1, w1h, w1l, C_, MLP_);
    wsplit_k<<<dim3(C_ / 32, MLP_ / 32), 256>>>(W2, w2h, w2l, MLP_, C_);
    asplit_k<<<(M_ * C_) / 1024, 256>>>(x1, x1h, x1l);
    asplit_k<<<(M_ * C_) / 1024, 256>>>(x2, x2h, x2l);

    // 1) q = x1 @ Wq + bq + pos_q
    tgemm<0><<<dim3(C_ / 128, M_ / 128), 256, TG_SMEM>>>(
        x1h, x1l, wqh, wql, bq, pos_q, q, nullptr, M_, C_, C_);
    // 2) kv = x2 @ Wkv + bkv ; k += pos_k ; split k/v
    tgemm<1><<<dim3(2 * C_ / 128, M_ / 128), 256, TG_SMEM>>>(
        x2h, x2l, wkvh, wkvl, bkv, pos_k, k, v, M_, 2 * C_, C_);
    // 3) kp/vp
    kvp_k<<<dim3(P_ / 64, B_ * H_, 2), 256>>>(k, v, Wp, bp, kp, vp);
    // 4) fused attention
    attn_k<<<dim3(B_ * H_, N1_ / 64), 256, ATT_SMEM_BYTES>>>(temp, xa);
    // 5) xn = l2norm(attn_out + q), plus bf16 split for MLP1
    l2n_k<<<M_ / 8, 256>>>(xa, q, xn, xnh, xnl);
    // 6) h = gelu(xn @ W1 + b1) -> bf16 split directly
    tgemm<2><<<dim3(MLP_ / 128, M_ / 128), 256, TG_SMEM>>>(
        xnh, xnl, w1h, w1l, b1, nullptr, hh, hl, M_, MLP_, C_);
    // 7) pre = h @ W2 + b2 + xn
    tgemm<3><<<dim3(C_ / 128, M_ / 128), 256, TG_SMEM>>>(
        hh, hl, w2h, w2l, b2, xn, xa, nullptr, M_, C_, MLP_);
    // 8) out = l2norm(pre)
    l2n_k<<<M_ / 8, 256>>>(xa, nullptr, (float*)d_out, nullptr, nullptr);
}